// round 1
// baseline (speedup 1.0000x reference)
#include <cuda_runtime.h>
#include <cstdint>
#include <cstddef>

#define OUT_FEAT 11008
#define IN_FEAT  4096
#define HAD      128
#define NBLK     (OUT_FEAT / HAD)   // 86

// Scratch for Z = blockdiag(R_right^T) @ inp  (180 MB, static device array: allowed)
__device__ float g_Z[(size_t)OUT_FEAT * IN_FEAT];
__device__ unsigned int g_absmax_bits;

// ---------------------------------------------------------------------------
// Kernel A: Z[b*128 + h', k] = sum_h R_right[h, h'] * inp[b*128 + h, k]
//   GEMM per batch b: M=128 (h'), N=4096 (k), K=128 (h)
//   A[m, kk] = R_right[kk, m]  (row-major contiguous in m -> direct coalesced)
//   B[kk, n] = inp[(b*128+kk)*IN_FEAT + n]
// grid: (IN_FEAT/128, NBLK), 256 threads. Also resets g_absmax_bits.
// ---------------------------------------------------------------------------
__global__ __launch_bounds__(256) void rot_block_kernel(
    const float* __restrict__ inp, const float* __restrict__ Rr)
{
    if (blockIdx.x == 0 && blockIdx.y == 0 && threadIdx.x == 0)
        g_absmax_bits = 0u;

    __shared__ float As[16][128];
    __shared__ float Bs[16][128];

    const int n0  = blockIdx.x * 128;
    const int b   = blockIdx.y;
    const int tid = threadIdx.x;
    const int tx  = tid & 15;   // 0..15 -> 8 cols each
    const int ty  = tid >> 4;   // 0..15 -> 8 rows each

    const float* Bptr = inp + (size_t)b * HAD * IN_FEAT;

    float acc[8][8];
#pragma unroll
    for (int i = 0; i < 8; i++)
#pragma unroll
        for (int j = 0; j < 8; j++) acc[i][j] = 0.0f;

    for (int k0 = 0; k0 < HAD; k0 += 16) {
#pragma unroll
        for (int l = 0; l < 2; l++) {
            int id = tid + l * 256;          // 0..511
            int r  = id >> 5;                // 0..15
            int c  = (id & 31) * 4;          // 0..124
            *(float4*)&As[r][c] = *(const float4*)&Rr[(k0 + r) * HAD + c];
            *(float4*)&Bs[r][c] = *(const float4*)&Bptr[(size_t)(k0 + r) * IN_FEAT + n0 + c];
        }
        __syncthreads();

#pragma unroll
        for (int kk = 0; kk < 16; kk++) {
            float a[8], bv[8];
            *(float4*)&a[0]  = *(float4*)&As[kk][ty * 8];
            *(float4*)&a[4]  = *(float4*)&As[kk][ty * 8 + 4];
            *(float4*)&bv[0] = *(float4*)&Bs[kk][tx * 8];
            *(float4*)&bv[4] = *(float4*)&Bs[kk][tx * 8 + 4];
#pragma unroll
            for (int i = 0; i < 8; i++)
#pragma unroll
                for (int j = 0; j < 8; j++)
                    acc[i][j] = fmaf(a[i], bv[j], acc[i][j]);
        }
        __syncthreads();
    }

    float* Cptr = g_Z + (size_t)b * HAD * IN_FEAT;
#pragma unroll
    for (int i = 0; i < 8; i++) {
        int row = ty * 8 + i;
        *(float4*)&Cptr[(size_t)row * IN_FEAT + n0 + tx * 8] =
            make_float4(acc[i][0], acc[i][1], acc[i][2], acc[i][3]);
        *(float4*)&Cptr[(size_t)row * IN_FEAT + n0 + tx * 8 + 4] =
            make_float4(acc[i][4], acc[i][5], acc[i][6], acc[i][7]);
    }
}

// ---------------------------------------------------------------------------
// Kernel B: Y = Z @ R_left   (M=11008, N=4096, K=4096)
//   Double-buffered 128x128 tiles, KT=16, 8x8 per thread.
//   Fused global abs-max (atomicMax on float bits, values >= 0).
// grid: (N/128, M/128) = (32, 86), 256 threads
// ---------------------------------------------------------------------------
__global__ __launch_bounds__(256) void gemm_absmax_kernel(
    const float* __restrict__ Rl, float* __restrict__ Y)
{
    __shared__ float As[2][16][128];
    __shared__ float Bs[2][16][128];
    __shared__ float red[8];

    const int n0  = blockIdx.x * 128;
    const int m0  = blockIdx.y * 128;
    const int tid = threadIdx.x;
    const int tx  = tid & 15;
    const int ty  = tid >> 4;

    const int K = IN_FEAT;  // 4096
    const int N = IN_FEAT;  // 4096
    const int NKT = K / 16; // 256

    // loader mapping (512 float4 per tile, 2 per thread)
    // A tile: r = id>>2 (0..127 rows of M), c = (id&3)*4 (k within tile)
    // B tile: r = id>>5 (0..15 rows of K),  c = (id&31)*4 (n within tile)

    float4 ra[2], rb[2];

    // prologue: tile 0 -> buffer 0
#pragma unroll
    for (int l = 0; l < 2; l++) {
        int id = tid + l * 256;
        {   int r = id >> 2, c = (id & 3) * 4;
            float4 v = *(const float4*)&g_Z[(size_t)(m0 + r) * K + c];
            As[0][c + 0][r] = v.x; As[0][c + 1][r] = v.y;
            As[0][c + 2][r] = v.z; As[0][c + 3][r] = v.w; }
        {   int r = id >> 5, c = (id & 31) * 4;
            *(float4*)&Bs[0][r][c] = *(const float4*)&Rl[(size_t)r * N + n0 + c]; }
    }
    __syncthreads();

    float acc[8][8];
#pragma unroll
    for (int i = 0; i < 8; i++)
#pragma unroll
        for (int j = 0; j < 8; j++) acc[i][j] = 0.0f;

    for (int kt = 0; kt < NKT; kt++) {
        const int cur = kt & 1;

        if (kt + 1 < NKT) {
            const int k0 = (kt + 1) * 16;
#pragma unroll
            for (int l = 0; l < 2; l++) {
                int id = tid + l * 256;
                int ar = id >> 2, ac = (id & 3) * 4;
                ra[l] = *(const float4*)&g_Z[(size_t)(m0 + ar) * K + k0 + ac];
                int br = id >> 5, bc = (id & 31) * 4;
                rb[l] = *(const float4*)&Rl[(size_t)(k0 + br) * N + n0 + bc];
            }
        }

#pragma unroll
        for (int kk = 0; kk < 16; kk++) {
            float a[8], bv[8];
            *(float4*)&a[0]  = *(float4*)&As[cur][kk][ty * 8];
            *(float4*)&a[4]  = *(float4*)&As[cur][kk][ty * 8 + 4];
            *(float4*)&bv[0] = *(float4*)&Bs[cur][kk][tx * 8];
            *(float4*)&bv[4] = *(float4*)&Bs[cur][kk][tx * 8 + 4];
#pragma unroll
            for (int i = 0; i < 8; i++)
#pragma unroll
                for (int j = 0; j < 8; j++)
                    acc[i][j] = fmaf(a[i], bv[j], acc[i][j]);
        }

        if (kt + 1 < NKT) {
            const int nxt = cur ^ 1;
#pragma unroll
            for (int l = 0; l < 2; l++) {
                int id = tid + l * 256;
                int ar = id >> 2, ac = (id & 3) * 4;
                As[nxt][ac + 0][ar] = ra[l].x; As[nxt][ac + 1][ar] = ra[l].y;
                As[nxt][ac + 2][ar] = ra[l].z; As[nxt][ac + 3][ar] = ra[l].w;
                int br = id >> 5, bc = (id & 31) * 4;
                *(float4*)&Bs[nxt][br][bc] = rb[l];
            }
        }
        __syncthreads();
    }

    // write C + local abs-max
    float lm = 0.0f;
#pragma unroll
    for (int i = 0; i < 8; i++) {
        int row = m0 + ty * 8 + i;
        *(float4*)&Y[(size_t)row * N + n0 + tx * 8] =
            make_float4(acc[i][0], acc[i][1], acc[i][2], acc[i][3]);
        *(float4*)&Y[(size_t)row * N + n0 + tx * 8 + 4] =
            make_float4(acc[i][4], acc[i][5], acc[i][6], acc[i][7]);
#pragma unroll
        for (int j = 0; j < 8; j++) lm = fmaxf(lm, fabsf(acc[i][j]));
    }

#pragma unroll
    for (int o = 16; o > 0; o >>= 1)
        lm = fmaxf(lm, __shfl_xor_sync(0xffffffffu, lm, o));
    if ((tid & 31) == 0) red[tid >> 5] = lm;
    __syncthreads();
    if (tid == 0) {
        float bm = red[0];
#pragma unroll
        for (int w = 1; w < 8; w++) bm = fmaxf(bm, red[w]);
        atomicMax(&g_absmax_bits, __float_as_uint(bm));
    }
}

// ---------------------------------------------------------------------------
// Kernel C: in-place symmetric int8 fake-quant of Y (d_out)
// ---------------------------------------------------------------------------
__global__ __launch_bounds__(256) void quant_kernel(float* __restrict__ Y, size_t n4)
{
    const float am = __uint_as_float(g_absmax_bits);
    const float s  = fmaxf(am / 127.0f, 1.17549435e-38f);
    size_t i = (size_t)blockIdx.x * blockDim.x + threadIdx.x;
    size_t stride = (size_t)gridDim.x * blockDim.x;
    for (; i < n4; i += stride) {
        float4 v = ((float4*)Y)[i];
        v.x = fminf(fmaxf(rintf(v.x / s), -127.0f), 127.0f) * s;
        v.y = fminf(fmaxf(rintf(v.y / s), -127.0f), 127.0f) * s;
        v.z = fminf(fmaxf(rintf(v.z / s), -127.0f), 127.0f) * s;
        v.w = fminf(fmaxf(rintf(v.w / s), -127.0f), 127.0f) * s;
        ((float4*)Y)[i] = v;
    }
}

// ---------------------------------------------------------------------------
extern "C" void kernel_launch(void* const* d_in, const int* in_sizes, int n_in,
                              void* d_out, int out_size)
{
    const float* inp = (const float*)d_in[0];   // (11008, 4096)
    const float* Rl  = (const float*)d_in[1];   // (4096, 4096)
    const float* Rr  = (const float*)d_in[2];   // (128, 128)
    float* Y = (float*)d_out;                   // (11008, 4096)

    // Kernel A: Z = blockdiag(Rr^T) @ inp  (+ reset absmax)
    dim3 gA(IN_FEAT / 128, NBLK);
    rot_block_kernel<<<gA, 256>>>(inp, Rr);

    // Kernel B: Y = Z @ R_left, fused absmax
    dim3 gB(IN_FEAT / 128, OUT_FEAT / 128);
    gemm_absmax_kernel<<<gB, 256>>>(Rl, Y);

    // Kernel C: quantize in place
    size_t n4 = (size_t)OUT_FEAT * IN_FEAT / 4;
    quant_kernel<<<2048, 256>>>(Y, n4);
}

// round 3
// speedup vs baseline: 1.3903x; 1.3903x over previous
#include <cuda_runtime.h>
#include <cstdint>
#include <cstddef>

#define OUT_FEAT 11008
#define IN_FEAT  4096
#define HAD      128
#define NBLK     (OUT_FEAT / HAD)   // 86
#define KD       IN_FEAT            // 4096 (GEMM K and N)
#define MT_TOT   (OUT_FEAT / 16)    // 688 m16 atoms
#define KT_TOT   (KD / 8)           // 512 k8 tiles
#define NP_TOT   (KD / 16)          // 256 n-atom pairs

// ---------------------------------------------------------------------------
// Static device scratch
// ---------------------------------------------------------------------------
__device__ float g_Z[(size_t)OUT_FEAT * KD];     // 180 MB fp32 rotated A
__device__ float g_Ahi[(size_t)OUT_FEAT * KD];   // frag-major tf32 hi
__device__ float g_Alo[(size_t)OUT_FEAT * KD];   // frag-major tf32 lo
__device__ float g_Bhi[(size_t)KD * KD];         // frag-major tf32 hi (B = Rl)
__device__ float g_Blo[(size_t)KD * KD];
__device__ unsigned int g_absmax_bits;

// ---------------------------------------------------------------------------
// Helpers
// ---------------------------------------------------------------------------
__device__ __forceinline__ uint32_t smem_u32(const void* p) {
    uint32_t a;
    asm("{ .reg .u64 t; cvta.to.shared.u64 t, %1; cvt.u32.u64 %0, t; }" : "=r"(a) : "l"(p));
    return a;
}
__device__ __forceinline__ float to_tf32(float x) {
    uint32_t u;
    asm("cvt.rna.tf32.f32 %0, %1;" : "=r"(u) : "f"(x));
    return __uint_as_float(u);
}
__device__ __forceinline__ void cp16(uint32_t dst, const void* src) {
    asm volatile("cp.async.cg.shared.global [%0], [%1], 16;" :: "r"(dst), "l"(src) : "memory");
}
#define CP_COMMIT() asm volatile("cp.async.commit_group;" ::: "memory")
#define CP_WAIT3()  asm volatile("cp.async.wait_group 3;" ::: "memory")

// m16n8k8 tf32 mma (sm_80+, valid in compute_100 PTX)
__device__ __forceinline__ void mma8(float* d, const uint32_t* a, const uint32_t* b) {
    asm volatile(
        "mma.sync.aligned.m16n8k8.row.col.f32.tf32.tf32.f32 "
        "{%0,%1,%2,%3}, {%4,%5,%6,%7}, {%8,%9}, {%0,%1,%2,%3};"
        : "+f"(d[0]), "+f"(d[1]), "+f"(d[2]), "+f"(d[3])
        : "r"(a[0]), "r"(a[1]), "r"(a[2]), "r"(a[3]), "r"(b[0]), "r"(b[1]));
}

// ---------------------------------------------------------------------------
// Kernel A: Z = blockdiag(R_right^T) @ inp   (fp32; also resets absmax)
// ---------------------------------------------------------------------------
__global__ __launch_bounds__(256) void rot_block_kernel(
    const float* __restrict__ inp, const float* __restrict__ Rr)
{
    if (blockIdx.x == 0 && blockIdx.y == 0 && threadIdx.x == 0)
        g_absmax_bits = 0u;

    __shared__ float As[16][128];
    __shared__ float Bs[16][128];

    const int n0  = blockIdx.x * 128;
    const int b   = blockIdx.y;
    const int tid = threadIdx.x;
    const int tx  = tid & 15;
    const int ty  = tid >> 4;

    const float* Bptr = inp + (size_t)b * HAD * IN_FEAT;

    float acc[8][8];
#pragma unroll
    for (int i = 0; i < 8; i++)
#pragma unroll
        for (int j = 0; j < 8; j++) acc[i][j] = 0.0f;

    for (int k0 = 0; k0 < HAD; k0 += 16) {
#pragma unroll
        for (int l = 0; l < 2; l++) {
            int id = tid + l * 256;
            int r  = id >> 5;
            int c  = (id & 31) * 4;
            *(float4*)&As[r][c] = *(const float4*)&Rr[(k0 + r) * HAD + c];
            *(float4*)&Bs[r][c] = *(const float4*)&Bptr[(size_t)(k0 + r) * IN_FEAT + n0 + c];
        }
        __syncthreads();
#pragma unroll
        for (int kk = 0; kk < 16; kk++) {
            float a[8], bv[8];
            *(float4*)&a[0]  = *(float4*)&As[kk][ty * 8];
            *(float4*)&a[4]  = *(float4*)&As[kk][ty * 8 + 4];
            *(float4*)&bv[0] = *(float4*)&Bs[kk][tx * 8];
            *(float4*)&bv[4] = *(float4*)&Bs[kk][tx * 8 + 4];
#pragma unroll
            for (int i = 0; i < 8; i++)
#pragma unroll
                for (int j = 0; j < 8; j++)
                    acc[i][j] = fmaf(a[i], bv[j], acc[i][j]);
        }
        __syncthreads();
    }

    float* Cptr = g_Z + (size_t)b * HAD * KD;
#pragma unroll
    for (int i = 0; i < 8; i++) {
        int row = ty * 8 + i;
        *(float4*)&Cptr[(size_t)row * KD + n0 + tx * 8]     = make_float4(acc[i][0], acc[i][1], acc[i][2], acc[i][3]);
        *(float4*)&Cptr[(size_t)row * KD + n0 + tx * 8 + 4] = make_float4(acc[i][4], acc[i][5], acc[i][6], acc[i][7]);
    }
}

// ---------------------------------------------------------------------------
// pack_A: Z (row-major) -> frag-major tf32 hi/lo
//   atom(mt, kt): lane owns a0=(g,tg) a1=(g+8,tg) a2=(g,tg+4) a3=(g+8,tg+4)
//   offset = ((kt*MT_TOT + mt)*32 + lane)*4
// grid = MT_TOT*64 blocks, 256 threads (warp w -> kt = ktg*8 + w)
// ---------------------------------------------------------------------------
__global__ __launch_bounds__(256) void pack_A_kernel()
{
    const int blk  = blockIdx.x;
    const int mt   = blk >> 6;
    const int ktg  = blk & 63;
    const int wid  = threadIdx.x >> 5;
    const int lane = threadIdx.x & 31;
    const int kt   = ktg * 8 + wid;
    const int g    = lane >> 2;
    const int tg   = lane & 3;

    const float* zp = g_Z + (size_t)(mt * 16 + g) * KD + kt * 8 + tg;
    float a0 = zp[0];
    float a1 = zp[(size_t)8 * KD];
    float a2 = zp[4];
    float a3 = zp[(size_t)8 * KD + 4];

    float h0 = to_tf32(a0), h1 = to_tf32(a1), h2 = to_tf32(a2), h3 = to_tf32(a3);
    float l0 = to_tf32(a0 - h0), l1 = to_tf32(a1 - h1), l2 = to_tf32(a2 - h2), l3 = to_tf32(a3 - h3);

    size_t o = ((size_t)(kt * MT_TOT + mt) * 32 + lane) * 4;
    *(float4*)&g_Ahi[o] = make_float4(h0, h1, h2, h3);
    *(float4*)&g_Alo[o] = make_float4(l0, l1, l2, l3);
}

// ---------------------------------------------------------------------------
// pack_B: Rl (K x N row-major) -> frag-major tf32 hi/lo, atoms paired along n
//   pair p covers n in [p*16, p*16+16): lane 16B = {bL0,bL1,bR0,bR1}
//   bL0 = Rl[kt*8+tg][p*16+g], bL1 = Rl[kt*8+tg+4][p*16+g], bR* at col +8
//   offset = ((kt*NP_TOT + p)*32 + lane)*4
// grid = KT_TOT*32 blocks, 256 threads (warp w -> p = pg*8 + w)
// ---------------------------------------------------------------------------
__global__ __launch_bounds__(256) void pack_B_kernel(const float* __restrict__ Rl)
{
    const int blk  = blockIdx.x;
    const int kt   = blk >> 5;
    const int pg   = blk & 31;
    const int wid  = threadIdx.x >> 5;
    const int lane = threadIdx.x & 31;
    const int p    = pg * 8 + wid;
    const int g    = lane >> 2;
    const int tg   = lane & 3;

    const float* rp = Rl + (size_t)(kt * 8 + tg) * KD + p * 16 + g;
    float b0 = rp[0];
    float b1 = rp[(size_t)4 * KD];
    float b2 = rp[8];
    float b3 = rp[(size_t)4 * KD + 8];

    float h0 = to_tf32(b0), h1 = to_tf32(b1), h2 = to_tf32(b2), h3 = to_tf32(b3);
    float l0 = to_tf32(b0 - h0), l1 = to_tf32(b1 - h1), l2 = to_tf32(b2 - h2), l3 = to_tf32(b3 - h3);

    size_t o = ((size_t)(kt * NP_TOT + p) * 32 + lane) * 4;
    *(float4*)&g_Bhi[o] = make_float4(h0, h1, h2, h3);
    *(float4*)&g_Blo[o] = make_float4(l0, l1, l2, l3);
}

// ---------------------------------------------------------------------------
// GEMM: Y = A @ B  via mma.sync tf32, 3-pass hi/lo.
//   BM=128 BN=256 BK=8, 5-stage cp.async, 8 warps (wm in {0,1}, wn in {0..3}),
//   warp tile 64x64 (4 m-atoms x 8 n-atoms). Fused global absmax.
// grid (16, 86), 256 threads.
// ---------------------------------------------------------------------------
#define STAGES     5
#define STG_FLOATS 6144          // A hi 1024 | A lo 1024 | B hi 2048 | B lo 2048
#define SM_AHI 0
#define SM_ALO 1024
#define SM_BHI 2048
#define SM_BLO 4096
#define GEMM_SMEM (STAGES * STG_FLOATS * 4)   // 122880 B

extern __shared__ float g_sm[];

__global__ __launch_bounds__(256, 1) void gemm_tf32_kernel(float* __restrict__ Y)
{
    const int tid  = threadIdx.x;
    const int lane = tid & 31;
    const int wid  = tid >> 5;
    const int wm   = wid & 1;    // m half (64 rows)
    const int wn   = wid >> 1;   // n quarter (64 cols)
    const int nb   = blockIdx.x; // 0..15
    const int mb   = blockIdx.y; // 0..85

    const float* gAhi = g_Ahi + (size_t)mb * 8 * 128;    // + kt*MT_TOT*128
    const float* gAlo = g_Alo + (size_t)mb * 8 * 128;
    const float* gBhi = g_Bhi + (size_t)nb * 16 * 128;   // + kt*NP_TOT*128
    const float* gBlo = g_Blo + (size_t)nb * 16 * 128;

    const uint32_t sbase = smem_u32(g_sm);

    float acc[4][8][4];
#pragma unroll
    for (int i = 0; i < 4; i++)
#pragma unroll
        for (int j = 0; j < 8; j++)
#pragma unroll
            for (int r = 0; r < 4; r++) acc[i][j][r] = 0.0f;

    // ---- stage loader (linear cp.async; 6 x 16B per thread per stage) ----
#define ISSUE_STAGE(KT)                                                           \
    {                                                                             \
        const int s_ = (KT) % STAGES;                                             \
        const uint32_t d_ = sbase + (uint32_t)(s_ * STG_FLOATS) * 4;              \
        const size_t ka_ = (size_t)(KT) * (MT_TOT * 128);                         \
        const size_t kb_ = (size_t)(KT) * (NP_TOT * 128);                         \
        cp16(d_ + (SM_AHI + tid * 4) * 4,          gAhi + ka_ + tid * 4);         \
        cp16(d_ + (SM_ALO + tid * 4) * 4,          gAlo + ka_ + tid * 4);         \
        cp16(d_ + (SM_BHI + tid * 4) * 4,          gBhi + kb_ + tid * 4);         \
        cp16(d_ + (SM_BHI + (256 + tid) * 4) * 4,  gBhi + kb_ + (256 + tid) * 4); \
        cp16(d_ + (SM_BLO + tid * 4) * 4,          gBlo + kb_ + tid * 4);         \
        cp16(d_ + (SM_BLO + (256 + tid) * 4) * 4,  gBlo + kb_ + (256 + tid) * 4); \
    }

#pragma unroll
    for (int s = 0; s < STAGES - 1; s++) { ISSUE_STAGE(s); CP_COMMIT(); }

    for (int kt = 0; kt < KT_TOT; kt++) {
        CP_WAIT3();
        __syncthreads();

        const int nkt = kt + STAGES - 1;
        if (nkt < KT_TOT) ISSUE_STAGE(nkt);
        CP_COMMIT();

        const float* st = g_sm + (kt % STAGES) * STG_FLOATS;

        uint32_t A[4][4], B[4][4];

        // ---- pass 1: hi * hi ----
#pragma unroll
        for (int am = 0; am < 4; am++) {
            float4 v = *(const float4*)&st[SM_AHI + (wm * 4 + am) * 128 + lane * 4];
            A[am][0] = __float_as_uint(v.x); A[am][1] = __float_as_uint(v.y);
            A[am][2] = __float_as_uint(v.z); A[am][3] = __float_as_uint(v.w);
        }
#pragma unroll
        for (int bp = 0; bp < 4; bp++) {
            float4 v = *(const float4*)&st[SM_BHI + (wn * 4 + bp) * 128 + lane * 4];
            B[bp][0] = __float_as_uint(v.x); B[bp][1] = __float_as_uint(v.y);
            B[bp][2] = __float_as_uint(v.z); B[bp][3] = __float_as_uint(v.w);
        }
#pragma unroll
        for (int am = 0; am < 4; am++)
#pragma unroll
            for (int bp = 0; bp < 4; bp++) {
                mma8(acc[am][bp * 2],     A[am], &B[bp][0]);
                mma8(acc[am][bp * 2 + 1], A[am], &B[bp][2]);
            }

        // ---- pass 2: lo * hi ----
#pragma unroll
        for (int am = 0; am < 4; am++) {
            float4 v = *(const float4*)&st[SM_ALO + (wm * 4 + am) * 128 + lane * 4];
            A[am][0] = __float_as_uint(v.x); A[am][1] = __float_as_uint(v.y);
            A[am][2] = __float_as_uint(v.z); A[am][3] = __float_as_uint(v.w);
        }
#pragma unroll
        for (int am = 0; am < 4; am++)
#pragma unroll
            for (int bp = 0; bp < 4; bp++) {
                mma8(acc[am][bp * 2],     A[am], &B[bp][0]);
                mma8(acc[am][bp * 2 + 1], A[am], &B[bp][2]);
            }

        // ---- pass 3: hi * lo ----
#pragma unroll
        for (int am = 0; am < 4; am++) {
            float4 v = *(const float4*)&st[SM_AHI + (wm * 4 + am) * 128 + lane * 4];
            A[am][0] = __float_as_uint(v.x); A[am][1] = __float_as_uint(v.y);
            A[am][2] = __float_as_uint(v.z); A[am][3] = __float_as_uint(v.w);
        }
#pragma unroll
        for (int bp = 0; bp < 4; bp++) {
            float4 v = *(const float4*)&st[SM_BLO + (wn * 4 + bp) * 128 + lane * 4];
            B[bp][0] = __float_as_uint(v.x); B[bp][1] = __float_as_uint(v.y);
            B[bp][2] = __float_as_uint(v.z); B[bp][3] = __float_as_uint(v.w);
        }
#pragma unroll
        for (int am = 0; am < 4; am++)
#pragma unroll
            for (int bp = 0; bp < 4; bp++) {
                mma8(acc[am][bp * 2],     A[am], &B[bp][0]);
                mma8(acc[am][bp * 2 + 1], A[am], &B[bp][2]);
            }
    }

    // ---- epilogue: direct stores + absmax ----
    const int g  = lane >> 2;
    const int tg = lane & 3;
    float lm = 0.0f;

#pragma unroll
    for (int am = 0; am < 4; am++) {
        const int row0 = mb * 128 + wm * 64 + am * 16 + g;
#pragma unroll
        for (int nt = 0; nt < 8; nt++) {
            const int col = nb * 256 + wn * 64 + nt * 8 + tg * 2;
            float c0 = acc[am][nt][0], c1 = acc[am][nt][1];
            float c2 = acc[am][nt][2], c3 = acc[am][nt][3];
            *(float2*)&Y[(size_t)row0 * KD + col]       = make_float2(c0, c1);
            *(float2*)&Y[(size_t)(row0 + 8) * KD + col] = make_float2(c2, c3);
            lm = fmaxf(lm, fmaxf(fmaxf(fabsf(c0), fabsf(c1)), fmaxf(fabsf(c2), fabsf(c3))));
        }
    }

    __shared__ float red[8];
#pragma unroll
    for (int o = 16; o > 0; o >>= 1)
        lm = fmaxf(lm, __shfl_xor_sync(0xffffffffu, lm, o));
    if (lane == 0) red[wid] = lm;
    __syncthreads();
    if (tid == 0) {
        float bm = red[0];
#pragma unroll
        for (int w = 1; w < 8; w++) bm = fmaxf(bm, red[w]);
        atomicMax(&g_absmax_bits, __float_as_uint(bm));
    }
}

// ---------------------------------------------------------------------------
// quant: in-place symmetric int8 fake-quant
// ---------------------------------------------------------------------------
__global__ __launch_bounds__(256) void quant_kernel(float* __restrict__ Y, size_t n4)
{
    const float am = __uint_as_float(g_absmax_bits);
    const float s  = fmaxf(am / 127.0f, 1.17549435e-38f);
    size_t i = (size_t)blockIdx.x * blockDim.x + threadIdx.x;
    size_t stride = (size_t)gridDim.x * blockDim.x;
    for (; i < n4; i += stride) {
        float4 v = ((float4*)Y)[i];
        v.x = fminf(fmaxf(rintf(v.x / s), -127.0f), 127.0f) * s;
        v.y = fminf(fmaxf(rintf(v.y / s), -127.0f), 127.0f) * s;
        v.z = fminf(fmaxf(rintf(v.z / s), -127.0f), 127.0f) * s;
        v.w = fminf(fmaxf(rintf(v.w / s), -127.0f), 127.0f) * s;
        ((float4*)Y)[i] = v;
    }
}

// ---------------------------------------------------------------------------
extern "C" void kernel_launch(void* const* d_in, const int* in_sizes, int n_in,
                              void* d_out, int out_size)
{
    const float* inp = (const float*)d_in[0];   // (11008, 4096)
    const float* Rl  = (const float*)d_in[1];   // (4096, 4096)
    const float* Rr  = (const float*)d_in[2];   // (128, 128)
    float* Y = (float*)d_out;

    static bool attr_set = false;
    if (!attr_set) {
        cudaFuncSetAttribute(gemm_tf32_kernel,
                             cudaFuncAttributeMaxDynamicSharedMemorySize, GEMM_SMEM);
        attr_set = true;
    }

    dim3 gA(IN_FEAT / 128, NBLK);
    rot_block_kernel<<<gA, 256>>>(inp, Rr);

    pack_A_kernel<<<MT_TOT * 64, 256>>>();
    pack_B_kernel<<<KT_TOT * 32, 256>>>(Rl);

    dim3 gG(KD / 256, OUT_FEAT / 128);   // (16, 86)
    gemm_tf32_kernel<<<gG, 256, GEMM_SMEM>>>(Y);

    size_t n4 = (size_t)OUT_FEAT * KD / 4;
    quant_kernel<<<2048, 256>>>(Y, n4);
}

// round 4
// speedup vs baseline: 1.5013x; 1.0799x over previous
#include <cuda_runtime.h>
#include <cstdint>
#include <cstddef>

#define OUT_FEAT 11008
#define IN_FEAT  4096
#define HAD      128
#define NBLK     (OUT_FEAT / HAD)   // 86
#define KD       IN_FEAT            // 4096 (GEMM K and N)
#define MT_TOT   (OUT_FEAT / 16)    // 688 m16 atoms
#define KT_TOT   (KD / 8)           // 512 k8 atoms
#define KT2_TOT  (KT_TOT / 2)       // 256 k16 stages
#define NP_TOT   (KD / 16)          // 256 n-atom pairs

// ---------------------------------------------------------------------------
// Static device scratch
// ---------------------------------------------------------------------------
__device__ float g_Z[(size_t)OUT_FEAT * KD];     // fp32 rotated A
__device__ float g_Ahi[(size_t)OUT_FEAT * KD];   // frag-major tf32 hi
__device__ float g_Alo[(size_t)OUT_FEAT * KD];   // frag-major tf32 lo
__device__ float g_Bhi[(size_t)KD * KD];         // frag-major tf32 hi (B = Rl)
__device__ float g_Blo[(size_t)KD * KD];
__device__ unsigned int g_absmax_bits;

// ---------------------------------------------------------------------------
// Helpers
// ---------------------------------------------------------------------------
__device__ __forceinline__ uint32_t smem_u32(const void* p) {
    uint32_t a;
    asm("{ .reg .u64 t; cvta.to.shared.u64 t, %1; cvt.u32.u64 %0, t; }" : "=r"(a) : "l"(p));
    return a;
}
__device__ __forceinline__ float to_tf32(float x) {
    uint32_t u;
    asm("cvt.rna.tf32.f32 %0, %1;" : "=r"(u) : "f"(x));
    return __uint_as_float(u);
}
__device__ __forceinline__ void cp16(uint32_t dst, const void* src) {
    asm volatile("cp.async.cg.shared.global [%0], [%1], 16;" :: "r"(dst), "l"(src) : "memory");
}
#define CP_COMMIT() asm volatile("cp.async.commit_group;" ::: "memory")
#define CP_WAIT2()  asm volatile("cp.async.wait_group 2;" ::: "memory")

// m16n8k8 tf32 mma (sm_80+, valid in compute_100 PTX)
__device__ __forceinline__ void mma8(float* d, const uint32_t* a, const uint32_t* b) {
    asm volatile(
        "mma.sync.aligned.m16n8k8.row.col.f32.tf32.tf32.f32 "
        "{%0,%1,%2,%3}, {%4,%5,%6,%7}, {%8,%9}, {%0,%1,%2,%3};"
        : "+f"(d[0]), "+f"(d[1]), "+f"(d[2]), "+f"(d[3])
        : "r"(a[0]), "r"(a[1]), "r"(a[2]), "r"(a[3]), "r"(b[0]), "r"(b[1]));
}

// ---------------------------------------------------------------------------
// Kernel A: Z = blockdiag(R_right^T) @ inp   (fp32; also resets absmax)
// ---------------------------------------------------------------------------
__global__ __launch_bounds__(256) void rot_block_kernel(
    const float* __restrict__ inp, const float* __restrict__ Rr)
{
    if (blockIdx.x == 0 && blockIdx.y == 0 && threadIdx.x == 0)
        g_absmax_bits = 0u;

    __shared__ float As[16][128];
    __shared__ float Bs[16][128];

    const int n0  = blockIdx.x * 128;
    const int b   = blockIdx.y;
    const int tid = threadIdx.x;
    const int tx  = tid & 15;
    const int ty  = tid >> 4;

    const float* Bptr = inp + (size_t)b * HAD * IN_FEAT;

    float acc[8][8];
#pragma unroll
    for (int i = 0; i < 8; i++)
#pragma unroll
        for (int j = 0; j < 8; j++) acc[i][j] = 0.0f;

    for (int k0 = 0; k0 < HAD; k0 += 16) {
#pragma unroll
        for (int l = 0; l < 2; l++) {
            int id = tid + l * 256;
            int r  = id >> 5;
            int c  = (id & 31) * 4;
            *(float4*)&As[r][c] = *(const float4*)&Rr[(k0 + r) * HAD + c];
            *(float4*)&Bs[r][c] = *(const float4*)&Bptr[(size_t)(k0 + r) * IN_FEAT + n0 + c];
        }
        __syncthreads();
#pragma unroll
        for (int kk = 0; kk < 16; kk++) {
            float a[8], bv[8];
            *(float4*)&a[0]  = *(float4*)&As[kk][ty * 8];
            *(float4*)&a[4]  = *(float4*)&As[kk][ty * 8 + 4];
            *(float4*)&bv[0] = *(float4*)&Bs[kk][tx * 8];
            *(float4*)&bv[4] = *(float4*)&Bs[kk][tx * 8 + 4];
#pragma unroll
            for (int i = 0; i < 8; i++)
#pragma unroll
                for (int j = 0; j < 8; j++)
                    acc[i][j] = fmaf(a[i], bv[j], acc[i][j]);
        }
        __syncthreads();
    }

    float* Cptr = g_Z + (size_t)b * HAD * KD;
#pragma unroll
    for (int i = 0; i < 8; i++) {
        int row = ty * 8 + i;
        *(float4*)&Cptr[(size_t)row * KD + n0 + tx * 8]     = make_float4(acc[i][0], acc[i][1], acc[i][2], acc[i][3]);
        *(float4*)&Cptr[(size_t)row * KD + n0 + tx * 8 + 4] = make_float4(acc[i][4], acc[i][5], acc[i][6], acc[i][7]);
    }
}

// ---------------------------------------------------------------------------
// pack_A: Z (row-major) -> frag-major tf32 hi/lo
// ---------------------------------------------------------------------------
__global__ __launch_bounds__(256) void pack_A_kernel()
{
    const int blk  = blockIdx.x;
    const int mt   = blk >> 6;
    const int ktg  = blk & 63;
    const int wid  = threadIdx.x >> 5;
    const int lane = threadIdx.x & 31;
    const int kt   = ktg * 8 + wid;
    const int g    = lane >> 2;
    const int tg   = lane & 3;

    const float* zp = g_Z + (size_t)(mt * 16 + g) * KD + kt * 8 + tg;
    float a0 = zp[0];
    float a1 = zp[(size_t)8 * KD];
    float a2 = zp[4];
    float a3 = zp[(size_t)8 * KD + 4];

    float h0 = to_tf32(a0), h1 = to_tf32(a1), h2 = to_tf32(a2), h3 = to_tf32(a3);
    float l0 = to_tf32(a0 - h0), l1 = to_tf32(a1 - h1), l2 = to_tf32(a2 - h2), l3 = to_tf32(a3 - h3);

    size_t o = ((size_t)(kt * MT_TOT + mt) * 32 + lane) * 4;
    *(float4*)&g_Ahi[o] = make_float4(h0, h1, h2, h3);
    *(float4*)&g_Alo[o] = make_float4(l0, l1, l2, l3);
}

// ---------------------------------------------------------------------------
// pack_B: Rl (K x N row-major) -> frag-major tf32 hi/lo, atoms paired along n
// ---------------------------------------------------------------------------
__global__ __launch_bounds__(256) void pack_B_kernel(const float* __restrict__ Rl)
{
    const int blk  = blockIdx.x;
    const int kt   = blk >> 5;
    const int pg   = blk & 31;
    const int wid  = threadIdx.x >> 5;
    const int lane = threadIdx.x & 31;
    const int p    = pg * 8 + wid;
    const int g    = lane >> 2;
    const int tg   = lane & 3;

    const float* rp = Rl + (size_t)(kt * 8 + tg) * KD + p * 16 + g;
    float b0 = rp[0];
    float b1 = rp[(size_t)4 * KD];
    float b2 = rp[8];
    float b3 = rp[(size_t)4 * KD + 8];

    float h0 = to_tf32(b0), h1 = to_tf32(b1), h2 = to_tf32(b2), h3 = to_tf32(b3);
    float l0 = to_tf32(b0 - h0), l1 = to_tf32(b1 - h1), l2 = to_tf32(b2 - h2), l3 = to_tf32(b3 - h3);

    size_t o = ((size_t)(kt * NP_TOT + p) * 32 + lane) * 4;
    *(float4*)&g_Bhi[o] = make_float4(h0, h1, h2, h3);
    *(float4*)&g_Blo[o] = make_float4(l0, l1, l2, l3);
}

// ---------------------------------------------------------------------------
// GEMM: Y = A @ B  via mma.sync tf32, 3-pass hi/lo.
//   BM=128 BN=256 BK=16 (2 k8-atoms/stage), 4-stage cp.async, 8 warps
//   (wm in {0,1}, wn in {0..3}), warp tile 64x64. Fused global absmax.
//   Pass order per k-atom: hi*hi -> lo*hi (B regs resident) -> hi*lo
//   (A-hi regs resident). 16 LDS.128 per warp per k-atom.
// grid (16, 86), 256 threads.
// ---------------------------------------------------------------------------
#define STAGES      4
#define ATOM_FLOATS 6144         // per k8-atom: Ahi 1024 | Alo 1024 | Bhi 2048 | Blo 2048
#define STG_FLOATS  (2 * ATOM_FLOATS)
#define SM_AHI 0
#define SM_ALO 1024
#define SM_BHI 2048
#define SM_BLO 4096
#define GEMM_SMEM (STAGES * STG_FLOATS * 4)   // 196608 B

extern __shared__ float g_sm[];

__global__ __launch_bounds__(256, 1) void gemm_tf32_kernel(float* __restrict__ Y)
{
    const int tid  = threadIdx.x;
    const int lane = tid & 31;
    const int wid  = tid >> 5;
    const int wm   = wid & 1;    // m half (64 rows)
    const int wn   = wid >> 1;   // n quarter (64 cols)
    const int nb   = blockIdx.x; // 0..15
    const int mb   = blockIdx.y; // 0..85

    const float* gAhi = g_Ahi + (size_t)mb * 8 * 128;    // + kt*MT_TOT*128
    const float* gAlo = g_Alo + (size_t)mb * 8 * 128;
    const float* gBhi = g_Bhi + (size_t)nb * 16 * 128;   // + kt*NP_TOT*128
    const float* gBlo = g_Blo + (size_t)nb * 16 * 128;

    const uint32_t sbase = smem_u32(g_sm);

    float acc[4][8][4];
#pragma unroll
    for (int i = 0; i < 4; i++)
#pragma unroll
        for (int j = 0; j < 8; j++)
#pragma unroll
            for (int r = 0; r < 4; r++) acc[i][j][r] = 0.0f;

    // ---- stage loader: 2 k8-atoms, 12 x 16B per thread per stage ----
#define ISSUE_STAGE(KT2)                                                              \
    {                                                                                 \
        const int s_ = (KT2) % STAGES;                                                \
        _Pragma("unroll")                                                             \
        for (int q_ = 0; q_ < 2; q_++) {                                              \
            const int k_ = (KT2) * 2 + q_;                                            \
            const uint32_t d_ = sbase + (uint32_t)(s_ * STG_FLOATS + q_ * ATOM_FLOATS) * 4; \
            const size_t ka_ = (size_t)k_ * (MT_TOT * 128);                           \
            const size_t kb_ = (size_t)k_ * (NP_TOT * 128);                           \
            cp16(d_ + (SM_AHI + tid * 4) * 4,          gAhi + ka_ + tid * 4);         \
            cp16(d_ + (SM_ALO + tid * 4) * 4,          gAlo + ka_ + tid * 4);         \
            cp16(d_ + (SM_BHI + tid * 4) * 4,          gBhi + kb_ + tid * 4);         \
            cp16(d_ + (SM_BHI + (256 + tid) * 4) * 4,  gBhi + kb_ + (256 + tid) * 4); \
            cp16(d_ + (SM_BLO + tid * 4) * 4,          gBlo + kb_ + tid * 4);         \
            cp16(d_ + (SM_BLO + (256 + tid) * 4) * 4,  gBlo + kb_ + (256 + tid) * 4); \
        }                                                                             \
    }

#pragma unroll
    for (int s = 0; s < STAGES - 1; s++) { ISSUE_STAGE(s); CP_COMMIT(); }

    for (int kt2 = 0; kt2 < KT2_TOT; kt2++) {
        CP_WAIT2();
        __syncthreads();

        const int nkt = kt2 + STAGES - 1;
        if (nkt < KT2_TOT) ISSUE_STAGE(nkt);
        CP_COMMIT();

#pragma unroll
        for (int q = 0; q < 2; q++) {
            const float* st = g_sm + ((kt2 % STAGES) * STG_FLOATS + q * ATOM_FLOATS);

            uint32_t Ah[4][4], Al[4][4], B[4][4];

            // load A-hi, A-lo, B-hi fragments (12 LDS.128)
#pragma unroll
            for (int am = 0; am < 4; am++) {
                float4 v = *(const float4*)&st[SM_AHI + (wm * 4 + am) * 128 + lane * 4];
                Ah[am][0] = __float_as_uint(v.x); Ah[am][1] = __float_as_uint(v.y);
                Ah[am][2] = __float_as_uint(v.z); Ah[am][3] = __float_as_uint(v.w);
            }
#pragma unroll
            for (int am = 0; am < 4; am++) {
                float4 v = *(const float4*)&st[SM_ALO + (wm * 4 + am) * 128 + lane * 4];
                Al[am][0] = __float_as_uint(v.x); Al[am][1] = __float_as_uint(v.y);
                Al[am][2] = __float_as_uint(v.z); Al[am][3] = __float_as_uint(v.w);
            }
#pragma unroll
            for (int bp = 0; bp < 4; bp++) {
                float4 v = *(const float4*)&st[SM_BHI + (wn * 4 + bp) * 128 + lane * 4];
                B[bp][0] = __float_as_uint(v.x); B[bp][1] = __float_as_uint(v.y);
                B[bp][2] = __float_as_uint(v.z); B[bp][3] = __float_as_uint(v.w);
            }

            // pass 1: hi * hi
#pragma unroll
            for (int am = 0; am < 4; am++)
#pragma unroll
                for (int bp = 0; bp < 4; bp++) {
                    mma8(acc[am][bp * 2],     Ah[am], &B[bp][0]);
                    mma8(acc[am][bp * 2 + 1], Ah[am], &B[bp][2]);
                }

            // pass 2: lo * hi (B-hi resident)
#pragma unroll
            for (int am = 0; am < 4; am++)
#pragma unroll
                for (int bp = 0; bp < 4; bp++) {
                    mma8(acc[am][bp * 2],     Al[am], &B[bp][0]);
                    mma8(acc[am][bp * 2 + 1], Al[am], &B[bp][2]);
                }

            // load B-lo over B regs (4 LDS.128), pass 3: hi * lo (A-hi resident)
#pragma unroll
            for (int bp = 0; bp < 4; bp++) {
                float4 v = *(const float4*)&st[SM_BLO + (wn * 4 + bp) * 128 + lane * 4];
                B[bp][0] = __float_as_uint(v.x); B[bp][1] = __float_as_uint(v.y);
                B[bp][2] = __float_as_uint(v.z); B[bp][3] = __float_as_uint(v.w);
            }
#pragma unroll
            for (int am = 0; am < 4; am++)
#pragma unroll
                for (int bp = 0; bp < 4; bp++) {
                    mma8(acc[am][bp * 2],     Ah[am], &B[bp][0]);
                    mma8(acc[am][bp * 2 + 1], Ah[am], &B[bp][2]);
                }
        }
    }

    // ---- epilogue: direct stores + absmax ----
    const int g  = lane >> 2;
    const int tg = lane & 3;
    float lm = 0.0f;

#pragma unroll
    for (int am = 0; am < 4; am++) {
        const int row0 = mb * 128 + wm * 64 + am * 16 + g;
#pragma unroll
        for (int nt = 0; nt < 8; nt++) {
            const int col = nb * 256 + wn * 64 + nt * 8 + tg * 2;
            float c0 = acc[am][nt][0], c1 = acc[am][nt][1];
            float c2 = acc[am][nt][2], c3 = acc[am][nt][3];
            *(float2*)&Y[(size_t)row0 * KD + col]       = make_float2(c0, c1);
            *(float2*)&Y[(size_t)(row0 + 8) * KD + col] = make_float2(c2, c3);
            lm = fmaxf(lm, fmaxf(fmaxf(fabsf(c0), fabsf(c1)), fmaxf(fabsf(c2), fabsf(c3))));
        }
    }

    __shared__ float red[8];
#pragma unroll
    for (int o = 16; o > 0; o >>= 1)
        lm = fmaxf(lm, __shfl_xor_sync(0xffffffffu, lm, o));
    if (lane == 0) red[wid] = lm;
    __syncthreads();
    if (tid == 0) {
        float bm = red[0];
#pragma unroll
        for (int w = 1; w < 8; w++) bm = fmaxf(bm, red[w]);
        atomicMax(&g_absmax_bits, __float_as_uint(bm));
    }
}

// ---------------------------------------------------------------------------
// quant: in-place symmetric int8 fake-quant
// ---------------------------------------------------------------------------
__global__ __launch_bounds__(256) void quant_kernel(float* __restrict__ Y, size_t n4)
{
    const float am = __uint_as_float(g_absmax_bits);
    const float s  = fmaxf(am / 127.0f, 1.17549435e-38f);
    size_t i = (size_t)blockIdx.x * blockDim.x + threadIdx.x;
    size_t stride = (size_t)gridDim.x * blockDim.x;
    for (; i < n4; i += stride) {
        float4 v = ((float4*)Y)[i];
        v.x = fminf(fmaxf(rintf(v.x / s), -127.0f), 127.0f) * s;
        v.y = fminf(fmaxf(rintf(v.y / s), -127.0f), 127.0f) * s;
        v.z = fminf(fmaxf(rintf(v.z / s), -127.0f), 127.0f) * s;
        v.w = fminf(fmaxf(rintf(v.w / s), -127.0f), 127.0f) * s;
        ((float4*)Y)[i] = v;
    }
}

// ---------------------------------------------------------------------------
extern "C" void kernel_launch(void* const* d_in, const int* in_sizes, int n_in,
                              void* d_out, int out_size)
{
    const float* inp = (const float*)d_in[0];   // (11008, 4096)
    const float* Rl  = (const float*)d_in[1];   // (4096, 4096)
    const float* Rr  = (const float*)d_in[2];   // (128, 128)
    float* Y = (float*)d_out;

    static bool attr_set = false;
    if (!attr_set) {
        cudaFuncSetAttribute(gemm_tf32_kernel,
                             cudaFuncAttributeMaxDynamicSharedMemorySize, GEMM_SMEM);
        attr_set = true;
    }

    dim3 gA(IN_FEAT / 128, NBLK);
    rot_block_kernel<<<gA, 256>>>(inp, Rr);

    pack_A_kernel<<<MT_TOT * 64, 256>>>();
    pack_B_kernel<<<KT_TOT * 32, 256>>>(Rl);

    dim3 gG(KD / 256, OUT_FEAT / 128);   // (16, 86)
    gemm_tf32_kernel<<<gG, 256, GEMM_SMEM>>>(Y);

    size_t n4 = (size_t)OUT_FEAT * KD / 4;
    quant_kernel<<<2048, 256>>>(Y, n4);
}